// round 1
// baseline (speedup 1.0000x reference)
#include <cuda_runtime.h>
#include <math.h>

#define NI 8192
#define NO 8192

// Scratch (allocation-free rule: __device__ globals)
__device__ float g_x[NI];
__device__ float g_logits[NO];

// ---------------------------------------------------------------------------
// Kernel 1: normalized pre-trace
// x[i] = (pre_trace[i]*sigmoid(d[i]) + spikes[i]) * (1 - sigmoid(d[i]))
// ---------------------------------------------------------------------------
__global__ void lis_prep_kernel(const float* __restrict__ spikes,
                                const float* __restrict__ trace,
                                const float* __restrict__ decay_raw) {
    int i = blockIdx.x * blockDim.x + threadIdx.x;
    if (i < NI) {
        float d  = 1.0f / (1.0f + expf(-decay_raw[i]));
        float nt = fmaf(trace[i], d, spikes[i]);
        g_x[i]   = nt * (1.0f - d);
    }
}

// ---------------------------------------------------------------------------
// Kernel 2: matvec. One warp per output row; x staged in SMEM per block.
// blockDim = 256 (8 warps/block), grid = NO/8 = 1024 blocks.
// Row read is fully coalesced float4 (512B per warp per iter).
// ---------------------------------------------------------------------------
__global__ void lis_matvec_kernel(const float* __restrict__ W,
                                  const float* __restrict__ bias) {
    __shared__ float sx[NI];
    for (int i = threadIdx.x; i < NI; i += blockDim.x)
        sx[i] = g_x[i];
    __syncthreads();

    const int warp = threadIdx.x >> 5;
    const int lane = threadIdx.x & 31;
    const int row  = blockIdx.x * 8 + warp;

    const float4* __restrict__ wrow = (const float4*)(W + (size_t)row * NI);
    const float4* xv = (const float4*)sx;

    float acc = 0.0f;
    #pragma unroll 8
    for (int k = lane; k < NI / 4; k += 32) {
        float4 w = __ldg(&wrow[k]);
        float4 x = xv[k];
        acc = fmaf(w.x, x.x, acc);
        acc = fmaf(w.y, x.y, acc);
        acc = fmaf(w.z, x.z, acc);
        acc = fmaf(w.w, x.w, acc);
    }

    #pragma unroll
    for (int off = 16; off; off >>= 1)
        acc += __shfl_down_sync(0xffffffffu, acc, off);

    if (lane == 0)
        g_logits[row] = acc + __ldg(&bias[row]);
}

// ---------------------------------------------------------------------------
// Kernel 3: softmax over 8192 logits. Single block of 1024 threads,
// 8 elements per thread, two block reductions (max, sum).
// ---------------------------------------------------------------------------
__global__ void lis_softmax_kernel(float* __restrict__ out) {
    __shared__ float red[32];
    const int tid  = threadIdx.x;
    const int lane = tid & 31;
    const int warp = tid >> 5;

    float vals[8];
    float lmax = -INFINITY;
    #pragma unroll
    for (int j = 0; j < 8; j++) {
        vals[j] = g_logits[tid + j * 1024];
        lmax = fmaxf(lmax, vals[j]);
    }

    // block max
    #pragma unroll
    for (int off = 16; off; off >>= 1)
        lmax = fmaxf(lmax, __shfl_xor_sync(0xffffffffu, lmax, off));
    if (lane == 0) red[warp] = lmax;
    __syncthreads();
    float m = red[lane];                 // 32 warps -> red[0..31]
    #pragma unroll
    for (int off = 16; off; off >>= 1)
        m = fmaxf(m, __shfl_xor_sync(0xffffffffu, m, off));
    __syncthreads();                     // red reuse barrier

    // block sum of exp
    float lsum = 0.0f;
    #pragma unroll
    for (int j = 0; j < 8; j++) {
        vals[j] = expf(vals[j] - m);
        lsum += vals[j];
    }
    #pragma unroll
    for (int off = 16; off; off >>= 1)
        lsum += __shfl_xor_sync(0xffffffffu, lsum, off);
    if (lane == 0) red[warp] = lsum;
    __syncthreads();
    float s = red[lane];
    #pragma unroll
    for (int off = 16; off; off >>= 1)
        s += __shfl_xor_sync(0xffffffffu, s, off);

    const float inv = 1.0f / s;
    #pragma unroll
    for (int j = 0; j < 8; j++)
        out[tid + j * 1024] = vals[j] * inv;
}

// ---------------------------------------------------------------------------
// Inputs (metadata order): in_spikes, pre_trace, weight, bias, pre_decay_raw
// Output: probs float[8192]
// ---------------------------------------------------------------------------
extern "C" void kernel_launch(void* const* d_in, const int* in_sizes, int n_in,
                              void* d_out, int out_size) {
    const float* in_spikes     = (const float*)d_in[0];
    const float* pre_trace     = (const float*)d_in[1];
    const float* weight        = (const float*)d_in[2];
    const float* bias          = (const float*)d_in[3];
    const float* pre_decay_raw = (const float*)d_in[4];
    float* out = (float*)d_out;

    lis_prep_kernel<<<NI / 256, 256>>>(in_spikes, pre_trace, pre_decay_raw);
    lis_matvec_kernel<<<NO / 8, 256>>>(weight, bias);
    lis_softmax_kernel<<<1, 1024>>>(out);
}